// round 16
// baseline (speedup 1.0000x reference)
#include <cuda_runtime.h>
#include <cstdint>

#define NP 256
#define NG 1024
#define F  128
#define EPSV 1e-5f

#define TP 32
#define TG 64
#define KC 32          // 4 chunks

// ---------------- f32x2 helpers ----------------
__device__ __forceinline__ unsigned long long fma2(unsigned long long a,
                                                   unsigned long long b,
                                                   unsigned long long c) {
    unsigned long long d;
    asm("fma.rn.f32x2 %0, %1, %2, %3;" : "=l"(d) : "l"(a), "l"(b), "l"(c));
    return d;
}
__device__ __forceinline__ unsigned long long dup2(float x) {
    unsigned long long d;
    asm("mov.b64 %0, {%1, %1};" : "=l"(d) : "f"(x));
    return d;
}
__device__ __forceinline__ float2 unpack2(unsigned long long v) {
    float2 r;
    asm("mov.b64 {%0, %1}, %2;" : "=f"(r.x), "=f"(r.y) : "l"(v));
    return r;
}

// ---------------- single fused kernel: prefetch + MOV-free mainloop ----------------
// out[p,g,c] = A[p,c] + B[g,c] + K[c] - 2 * sum_f (p_f * w'_cf) * g_f
// Accumulator f32x2 lanes = (g, g+1). Probe operands (w'_c * p_f) are duplicated
// into smem during the store phase; mainloop = 3 LDS.128 + 8 FFMA2 per f, no MOVs.
__global__ void __launch_bounds__(256) cls_kernel(
    const float* __restrict__ probe, const float* __restrict__ gal,
    const float* __restrict__ bnw, const float* __restrict__ bnb,
    const float* __restrict__ bnm, const float* __restrict__ bnv,
    const float* __restrict__ W, const float* __restrict__ bias,
    float* __restrict__ out)
{
    // sPd row = 66 u64 = 528 B (33*16); sG row = 68 fl = 272 B (17*16). All 16B
    // accesses land on 16B boundaries. Total ~27 KB static.
    __shared__ __align__(16) unsigned long long sPd[KC + 1][2 * TP + 2]; // [f][2p+c] dup'd
    __shared__ __align__(16) float sG[KC + 1][TG + 4];                   // [f][g] raw
    __shared__ float2 sA[TP];
    __shared__ float2 sB[TG];

    const int tid  = threadIdx.x;
    const int lane = tid & 31;
    const int warp = tid >> 5;
    const int bp = blockIdx.y * TP;
    const int bg = blockIdx.x * TG;

    // ======== PREFETCH: all 48 data LDGs issued up-front (MLP ~48) ========
    float px[4][4];   // [chunk][k]: probe row p = warp + 8k, f = KC*c + lane
    float gx[4][8];   // [chunk][k]: gallery row g = warp + 8k
    #pragma unroll
    for (int c = 0; c < 4; c++) {
        #pragma unroll
        for (int k = 0; k < 4; k++)
            px[c][k] = probe[(size_t)(bp + warp + 8 * k) * F + c * KC + lane];
        #pragma unroll
        for (int k = 0; k < 8; k++)
            gx[c][k] = gal[(size_t)(bg + warp + 8 * k) * F + c * KC + lane];
    }

    // -------- folded weights (lane f-stripe: f = lane + 32i) + K reduction --------
    float w0r[4], w1r[4];
    float kc0 = 0.f, kc1 = 0.f;
    #pragma unroll
    for (int i = 0; i < 4; i++) {
        const int f = lane + 32 * i;
        const float inv = bnw[f] * rsqrtf(bnv[f] + EPSV);
        const float Wf0 = W[f], Wf1 = W[F + f];
        w0r[i] = Wf0 * inv;
        w1r[i] = Wf1 * inv;
        const float off = bnb[f] - bnm[f] * inv;
        kc0 = fmaf(Wf0, off, kc0);
        kc1 = fmaf(Wf1, off, kc1);
    }
    #pragma unroll
    for (int o = 16; o > 0; o >>= 1) {
        kc0 += __shfl_xor_sync(0xffffffffu, kc0, o);
        kc1 += __shfl_xor_sync(0xffffffffu, kc1, o);
    }
    kc0 += bias[0];
    kc1 += bias[1];

    // -------- thread mapping: 2 probes x 4 gallery x 2 classes --------
    const int ty = tid >> 4;      // 0..15 -> probe pair
    const int tx = tid & 15;      // 0..15 -> gallery quad
    const int tp = 2 * ty;
    const int tg = 4 * tx;

    unsigned long long A0a = 0, A0b = 0, A1a = 0, A1b = 0;  // probe tp  : c0/c1 x (g01)/(g23)
    unsigned long long B0a = 0, B0b = 0, B1a = 0, B1b = 0;  // probe tp+1

    float pa0[4], pa1[4];
    float gb0[8], gb1[8];
    #pragma unroll
    for (int k = 0; k < 4; k++) { pa0[k] = 0.f; pa1[k] = 0.f; }
    #pragma unroll
    for (int k = 0; k < 8; k++) { gb0[k] = 0.f; gb1[k] = 0.f; }

    #pragma unroll
    for (int c = 0; c < 4; c++) {
        const float wc0 = w0r[c], wc1 = w1r[c];   // lane's folded weights, f = c*KC + lane

        // ---- probes: scale + DUPLICATE from registers into smem; fused A partials ----
        #pragma unroll
        for (int k = 0; k < 4; k++) {
            const int p = warp + 8 * k;
            const float x = px[c][k];
            const float s0 = x * wc0, s1 = x * wc1;
            *(ulonglong2*)&sPd[lane][2 * p] = make_ulonglong2(dup2(s0), dup2(s1));
            pa0[k] = fmaf(s0, x, pa0[k]);
            pa1[k] = fmaf(s1, x, pa1[k]);
        }
        // ---- gallery: store raw from registers; fused B partials ----
        #pragma unroll
        for (int k = 0; k < 8; k++) {
            const int g = warp + 8 * k;
            const float x = gx[c][k];
            sG[lane][g] = x;
            gb0[k] = fmaf(wc0 * x, x, gb0[k]);
            gb1[k] = fmaf(wc1 * x, x, gb1[k]);
        }
        __syncthreads();

        // ---- mainloop: 3 LDS.128 + 8 FFMA2 per f, zero MOVs ----
        ulonglong2 Pa = *(const ulonglong2*)&sPd[0][2 * tp];       // probe tp : (c0d,c1d)
        ulonglong2 Pb = *(const ulonglong2*)&sPd[0][2 * tp + 2];   // probe tp+1
        ulonglong2 G  = *(const ulonglong2*)&sG[0][tg];            // (g0,g1),(g2,g3)
        #pragma unroll
        for (int f = 0; f < KC; f++) {
            const ulonglong2 Pan = *(const ulonglong2*)&sPd[f + 1][2 * tp];     // row KC = pad
            const ulonglong2 Pbn = *(const ulonglong2*)&sPd[f + 1][2 * tp + 2];
            const ulonglong2 Gn  = *(const ulonglong2*)&sG[f + 1][tg];
            A0a = fma2(Pa.x, G.x, A0a);
            A0b = fma2(Pa.x, G.y, A0b);
            A1a = fma2(Pa.y, G.x, A1a);
            A1b = fma2(Pa.y, G.y, A1b);
            B0a = fma2(Pb.x, G.x, B0a);
            B0b = fma2(Pb.x, G.y, B0b);
            B1a = fma2(Pb.y, G.x, B1a);
            B1b = fma2(Pb.y, G.y, B1b);
            Pa = Pan; Pb = Pbn; G = Gn;
        }
        __syncthreads();
    }

    // -------- reduce A/B partials across lanes into smem --------
    #pragma unroll
    for (int k = 0; k < 4; k++) {
        float r0 = pa0[k], r1 = pa1[k];
        #pragma unroll
        for (int o = 16; o > 0; o >>= 1) {
            r0 += __shfl_down_sync(0xffffffffu, r0, o);
            r1 += __shfl_down_sync(0xffffffffu, r1, o);
        }
        if (lane == 0) sA[warp + 8 * k] = make_float2(r0, r1);
    }
    #pragma unroll
    for (int k = 0; k < 8; k++) {
        float r0 = gb0[k], r1 = gb1[k];
        #pragma unroll
        for (int o = 16; o > 0; o >>= 1) {
            r0 += __shfl_down_sync(0xffffffffu, r0, o);
            r1 += __shfl_down_sync(0xffffffffu, r1, o);
        }
        if (lane == 0) sB[warp + 8 * k] = make_float2(r0, r1);
    }
    __syncthreads();

    // -------- epilogue --------
    float2 Bv[4];
    #pragma unroll
    for (int j = 0; j < 4; j++) Bv[j] = sB[tg + j];

    #pragma unroll
    for (int i = 0; i < 2; i++) {
        const float2 Ap = sA[tp + i];
        const float ax = Ap.x + kc0;
        const float ay = Ap.y + kc1;
        const float2 c0a = unpack2(i == 0 ? A0a : B0a);   // c0 @ (g0,g1)
        const float2 c0b = unpack2(i == 0 ? A0b : B0b);   // c0 @ (g2,g3)
        const float2 c1a = unpack2(i == 0 ? A1a : B1a);   // c1 @ (g0,g1)
        const float2 c1b = unpack2(i == 0 ? A1b : B1b);   // c1 @ (g2,g3)
        float4 o0, o1;
        o0.x = fmaf(-2.0f, c0a.x, ax + Bv[0].x);
        o0.y = fmaf(-2.0f, c1a.x, ay + Bv[0].y);
        o0.z = fmaf(-2.0f, c0a.y, ax + Bv[1].x);
        o0.w = fmaf(-2.0f, c1a.y, ay + Bv[1].y);
        o1.x = fmaf(-2.0f, c0b.x, ax + Bv[2].x);
        o1.y = fmaf(-2.0f, c1b.x, ay + Bv[2].y);
        o1.z = fmaf(-2.0f, c0b.y, ax + Bv[3].x);
        o1.w = fmaf(-2.0f, c1b.y, ay + Bv[3].y);
        float4* dst = (float4*)(out + ((size_t)(bp + tp + i) * NG + bg + tg) * 2);
        dst[0] = o0;
        dst[1] = o1;
    }
}

// ---------------- launch: ONE kernel ----------------
extern "C" void kernel_launch(void* const* d_in, const int* in_sizes, int n_in,
                              void* d_out, int out_size) {
    const float* probe = (const float*)d_in[0];
    const float* gal   = (const float*)d_in[1];
    const float* bnw   = (const float*)d_in[2];
    const float* bnb   = (const float*)d_in[3];
    const float* bnm   = (const float*)d_in[4];
    const float* bnv   = (const float*)d_in[5];
    const float* W     = (const float*)d_in[6];
    const float* bias  = (const float*)d_in[7];
    float* out = (float*)d_out;

    dim3 grid(NG / TG, NP / TP);   // (16, 8) = 128 blocks x 256 threads
    cls_kernel<<<grid, 256>>>(probe, gal, bnw, bnb, bnm, bnv, W, bias, out);
}